// round 12
// baseline (speedup 1.0000x reference)
#include <cuda_runtime.h>
#include <cuda_bf16.h>
#include <cstdint>
#include <math.h>

#define NMAX 50000
#define EMAX 800000
#define ELLW 64   // padded ELL width (max in-degree; Poisson(16) -> P(>=64) ~ 0)

typedef unsigned long long ull;
typedef unsigned char u8;
typedef unsigned int u32;

// ---------------- scratch (static device globals; no allocation) ----------------
__device__ u8    g_m1h [NMAX * 128 * 2];   // gelu(x@W0+b0) bf16 hi
__device__ u8    g_m1l [NMAX * 128 * 2];
__device__ u8    g_m2h [NMAX * 128 * 2];   // gelu(agg1+bg2) bf16 hi
__device__ u8    g_m2l [NMAX * 128 * 2];
__device__ float g_q1  [NMAX * 128];
__device__ float g_p1  [NMAX * 128];
__device__ float g_q2  [NMAX * 64];
__device__ float g_p2  [NMAX * 64];
__device__ int   g_cur [NMAX];
__device__ int   g_ell [NMAX * ELLW];
// 8 weight panels (64 cols x 128 k, Wt[n][k] bf16, 272B row pad): [hi 17408][lo 17408]
#define PANEL_SZ 34816
__device__ u8    g_wimg[8 * PANEL_SZ];

__device__ __forceinline__ float gelu_erf(float x) {
    return 0.5f * x * (1.0f + erff(x * 0.7071067811865476f));
}

// packed fp32x2 helpers (pull kernels)
__device__ __forceinline__ ull ffma2(ull a, ull b, ull c) {
    ull d;
    asm("fma.rn.f32x2 %0, %1, %2, %3;" : "=l"(d) : "l"(a), "l"(b), "l"(c));
    return d;
}
__device__ __forceinline__ ull add2(ull a, ull b) {
    ull d;
    asm("add.rn.f32x2 %0, %1, %2;" : "=l"(d) : "l"(a), "l"(b));
    return d;
}
__device__ __forceinline__ ull dup2(float w) {
    ull d;
    asm("mov.b64 %0, {%1, %1};" : "=l"(d) : "f"(w));
    return d;
}
__device__ __forceinline__ ull pack2(float lo, float hi) {
    ull d;
    asm("mov.b64 %0, {%1, %2};" : "=l"(d) : "f"(lo), "f"(hi));
    return d;
}
__device__ __forceinline__ void unpack2(ull v, float& lo, float& hi) {
    asm("mov.b64 {%0, %1}, %2;" : "=f"(lo), "=f"(hi) : "l"(v));
}
__device__ __forceinline__ float ex2f(float x) {
    float r;
    asm("ex2.approx.ftz.f32 %0, %1;" : "=f"(r) : "f"(x));
    return r;
}

__device__ __forceinline__ u32 smem_u32(const void* p) {
    u32 a;
    asm("{ .reg .u64 t; cvta.to.shared.u64 t, %1; cvt.u32.u64 %0, t; }" : "=r"(a) : "l"(p));
    return a;
}

// ldmatrix x4 (non-trans)
__device__ __forceinline__ void ldm4(u32* r, u32 addr) {
    asm volatile("ldmatrix.sync.aligned.m8n8.x4.shared.b16 {%0,%1,%2,%3}, [%4];"
                 : "=r"(r[0]), "=r"(r[1]), "=r"(r[2]), "=r"(r[3]) : "r"(addr));
}
// m16n8k16 bf16 mma, fp32 accum
__device__ __forceinline__ void mma16816(float* d, const u32* a, u32 b0, u32 b1) {
    asm volatile("mma.sync.aligned.m16n8k16.row.col.f32.bf16.bf16.f32 "
                 "{%0,%1,%2,%3}, {%4,%5,%6,%7}, {%8,%9}, {%0,%1,%2,%3};"
                 : "+f"(d[0]), "+f"(d[1]), "+f"(d[2]), "+f"(d[3])
                 : "r"(a[0]), "r"(a[1]), "r"(a[2]), "r"(a[3]), "r"(b0), "r"(b1));
}

__device__ __forceinline__ void split_bf16(float v, __nv_bfloat16& h, __nv_bfloat16& l) {
    h = __float2bfloat16(v);
    l = __float2bfloat16(v - __bfloat162float(h));
}

// ---------------- prep: 8 weight panels (Wt[n][k] hi/lo) + cur zero ----------------
__global__ void prep_k(const float* __restrict__ W0,
                       const float* __restrict__ Wq1, const float* __restrict__ Wp1,
                       const float* __restrict__ Wq2, const float* __restrict__ Wp2,
                       u8* __restrict__ img, int* __restrict__ cur, int nnodes)
{
    const int i = blockIdx.x * blockDim.x + threadIdx.x;   // 0..65535
    if (i < nnodes) cur[i] = 0;
    const int p = i >> 13;          // panel 0..7
    const int idx = i & 8191;
    const int n = idx >> 7, k = idx & 127;
    float v;
    switch (p) {
        case 0: v = W0 [k * 128 + n];        break;
        case 1: v = W0 [k * 128 + 64 + n];   break;
        case 2: v = Wq1[k * 128 + n];        break;
        case 3: v = Wq1[k * 128 + 64 + n];   break;
        case 4: v = Wp1[k * 128 + n];        break;
        case 5: v = Wp1[k * 128 + 64 + n];   break;
        case 6: v = Wq2[k * 64 + n];         break;
        default: v = Wp2[k * 64 + n];        break;
    }
    __nv_bfloat16 h, l;
    split_bf16(v, h, l);
    u8* base = img + p * PANEL_SZ + n * 272 + k * 2;
    *(__nv_bfloat16*)(base)         = h;
    *(__nv_bfloat16*)(base + 17408) = l;
}

// ---------------- ELL build ----------------
__global__ void ell_fill_k(const int* __restrict__ src, const int* __restrict__ dst,
                           int* __restrict__ cur, int* __restrict__ ell, int E)
{
    const int e = blockIdx.x * blockDim.x + threadIdx.x;
    if (e < E) {
        const int d = dst[e];
        const int pos = atomicAdd(cur + d, 1);
        if (pos < ELLW) ell[(size_t)d * ELLW + pos] = src[e];
    }
}

// ---------------- mma.sync GEMM: 128 rows x 64 cols x K=128 per block ----------------
// A (bf16 hi/lo [N][128] global; or fp32 if AFP32) @ W panel y -> out cols [64*idx, +64).
// bf16x3: D = Ah*Wh + Ah*Wl + Al*Wh. Double-buffered ldmatrix pipeline over 8 k-steps.
// EPIBF: gelu + split into (outA=hi, outB=lo) bf16; else fp32 to (y<S ? outA : outB).
#define OFF_BIAS 0
#define OFF_AH   512
#define OFF_AL   (512 + 34816)
#define OFF_WH   (512 + 2 * 34816)
#define OFF_WL   (512 + 2 * 34816 + 17408)
#define GSMEM_SZ (512 + 2 * 34816 + 2 * 17408)

template<bool EPIBF, bool AFP32>
__global__ void __launch_bounds__(256, 2) mma_gemm_k(
    const u8* __restrict__ Ah, const u8* __restrict__ Al,
    const float* __restrict__ Af,
    const u8* __restrict__ img,
    const float* __restrict__ bias0, const float* __restrict__ bias1,
    void* outA, void* outB,
    int S, int ostride, int nrows)
{
    extern __shared__ char smem[];
    const u32 sb = smem_u32(smem);
    const int tid = threadIdx.x;
    const int wid = tid >> 5;
    const int lane = tid & 31;
    const int row0 = blockIdx.x * 128;
    const int y = blockIdx.y;
    const int idx = (y < S) ? y : y - S;
    const int col0 = 64 * idx;
    const float* bias = ((y < S) ? bias0 : bias1) + 64 * idx;
    float* fout = (float*)((y < S) ? outA : outB);

    // bias
    if (tid < 64) *(float*)(smem + OFF_BIAS + tid * 4) = bias[tid];

    // W panel copy (already in final layout): hi+lo = 2176 x 16B
    {
        const uint4* s = (const uint4*)(img + (size_t)y * PANEL_SZ);
        uint4* d = (uint4*)(smem + OFF_WH);
        #pragma unroll
        for (int i = tid; i < 2176; i += 256) d[i] = s[i];
    }
    // A copy: 128 rows x 16 chunks (16B bf16 = 8 values) x {hi,lo}
    if (AFP32) {
        for (int c = tid; c < 2048; c += 256) {
            const int r = c >> 4, cc = c & 15;
            int row = row0 + r;
            if (row >= nrows) row = nrows - 1;
            const float4 v0 = ((const float4*)Af)[(size_t)row * 32 + cc * 2];
            const float4 v1 = ((const float4*)Af)[(size_t)row * 32 + cc * 2 + 1];
            __nv_bfloat16 h[8], l[8];
            split_bf16(v0.x, h[0], l[0]); split_bf16(v0.y, h[1], l[1]);
            split_bf16(v0.z, h[2], l[2]); split_bf16(v0.w, h[3], l[3]);
            split_bf16(v1.x, h[4], l[4]); split_bf16(v1.y, h[5], l[5]);
            split_bf16(v1.z, h[6], l[6]); split_bf16(v1.w, h[7], l[7]);
            *(uint4*)(smem + OFF_AH + r * 272 + cc * 16) = *(uint4*)h;
            *(uint4*)(smem + OFF_AL + r * 272 + cc * 16) = *(uint4*)l;
        }
    } else {
        const uint4* sh = (const uint4*)Ah;
        const uint4* sl = (const uint4*)Al;
        for (int c = tid; c < 2048; c += 256) {
            const int r = c >> 4, cc = c & 15;
            int row = row0 + r;
            if (row >= nrows) row = nrows - 1;
            *(uint4*)(smem + OFF_AH + r * 272 + cc * 16) = sh[(size_t)row * 16 + cc];
            *(uint4*)(smem + OFF_AL + r * 272 + cc * 16) = sl[(size_t)row * 16 + cc];
        }
    }
    __syncthreads();

    const int wm = (wid & 3) * 32;   // warp row base
    const int wn = (wid >> 2) * 32;  // warp col base
    const int g   = lane >> 2;
    const int tig = lane & 3;

    // accumulators init from bias
    float acc[2][4][4];
    #pragma unroll
    for (int nt = 0; nt < 4; nt++) {
        const float2 bv = *(const float2*)(smem + OFF_BIAS + (wn + nt * 8 + 2 * tig) * 4);
        #pragma unroll
        for (int mt = 0; mt < 2; mt++) {
            acc[mt][nt][0] = bv.x; acc[mt][nt][1] = bv.y;
            acc[mt][nt][2] = bv.x; acc[mt][nt][3] = bv.y;
        }
    }

    // ldmatrix base addresses
    const u32 aOff = (u32)((wm + (lane & 15)) * 272 + ((lane >> 4) << 4));
    const u32 aH = sb + OFF_AH + aOff;
    const u32 aL = sb + OFF_AL + aOff;
    const u32 bOff = (u32)((wn + (lane & 7) + ((lane >> 4) << 3)) * 272 + (((lane >> 3) & 1) << 4));
    const u32 bH = sb + OFF_WH + bOff;
    const u32 bL = sb + OFF_WL + bOff;

    // double-buffered operand regs: opA = {ah0, ah1, al0, al1}, opB = {bh01, bh23, bl01, bl23}
    u32 opA[2][4][4], opB[2][4][4];
    #define LOAD_STEP(buf, s) do { \
        const u32 ko = (u32)((s) * 32); \
        ldm4(opA[buf][0], aH + ko); \
        ldm4(opA[buf][1], aH + ko + 16 * 272); \
        ldm4(opA[buf][2], aL + ko); \
        ldm4(opA[buf][3], aL + ko + 16 * 272); \
        ldm4(opB[buf][0], bH + ko); \
        ldm4(opB[buf][1], bH + ko + 16 * 272); \
        ldm4(opB[buf][2], bL + ko); \
        ldm4(opB[buf][3], bL + ko + 16 * 272); \
    } while (0)

    LOAD_STEP(0, 0);
    #pragma unroll
    for (int s = 0; s < 8; s++) {
        const int cur = s & 1, nxt = cur ^ 1;
        if (s < 7) LOAD_STEP(nxt, s + 1);
        #pragma unroll
        for (int mt = 0; mt < 2; mt++) {
            #pragma unroll
            for (int nt = 0; nt < 4; nt++) {
                const int pr = nt >> 1, h = (nt & 1) * 2;
                mma16816(acc[mt][nt], opA[cur][mt],     opB[cur][pr][h],     opB[cur][pr][h + 1]);
                mma16816(acc[mt][nt], opA[cur][mt],     opB[cur][2 + pr][h], opB[cur][2 + pr][h + 1]);
                mma16816(acc[mt][nt], opA[cur][2 + mt], opB[cur][pr][h],     opB[cur][pr][h + 1]);
            }
        }
    }
    #undef LOAD_STEP

    // epilogue
    #pragma unroll
    for (int mt = 0; mt < 2; mt++) {
        #pragma unroll
        for (int nt = 0; nt < 4; nt++) {
            const int r1 = row0 + wm + mt * 16 + g;
            const int r2 = r1 + 8;
            const int col = col0 + wn + nt * 8 + 2 * tig;
            float d0 = acc[mt][nt][0], d1 = acc[mt][nt][1];
            float d2 = acc[mt][nt][2], d3 = acc[mt][nt][3];
            if (EPIBF) {
                d0 = gelu_erf(d0); d1 = gelu_erf(d1);
                d2 = gelu_erf(d2); d3 = gelu_erf(d3);
                __nv_bfloat16 h0, h1, h2, h3, l0, l1, l2, l3;
                split_bf16(d0, h0, l0); split_bf16(d1, h1, l1);
                split_bf16(d2, h2, l2); split_bf16(d3, h3, l3);
                u8* oh = (u8*)outA; u8* ol = (u8*)outB;
                if (r1 < nrows) {
                    __nv_bfloat162 ph = __nv_bfloat162(h0, h1), pl = __nv_bfloat162(l0, l1);
                    *(u32*)(oh + ((size_t)r1 * 128 + col) * 2) = *(u32*)&ph;
                    *(u32*)(ol + ((size_t)r1 * 128 + col) * 2) = *(u32*)&pl;
                }
                if (r2 < nrows) {
                    __nv_bfloat162 ph = __nv_bfloat162(h2, h3), pl = __nv_bfloat162(l2, l3);
                    *(u32*)(oh + ((size_t)r2 * 128 + col) * 2) = *(u32*)&ph;
                    *(u32*)(ol + ((size_t)r2 * 128 + col) * 2) = *(u32*)&pl;
                }
            } else {
                if (r1 < nrows) *(float2*)(fout + (size_t)r1 * ostride + col) = make_float2(d0, d1);
                if (r2 < nrows) *(float2*)(fout + (size_t)r2 * ostride + col) = make_float2(d2, d3);
            }
        }
    }
}

// ---------------- fused GAT pull: warp per dst node, packed f32x2 math ----------------
// M2OUT: epilogue writes gelu(acc/den + inbias) split to bf16 hi/lo (m2h/m2l).
template<int D, bool BIAS, bool M2OUT>
__global__ void __launch_bounds__(256) gat_pull_k(
    const float* __restrict__ q, const float* __restrict__ p,
    const float* __restrict__ a,
    const int* __restrict__ degp, const int* __restrict__ ell,
    const float* __restrict__ outbias,
    float* __restrict__ out, u8* __restrict__ outh, u8* __restrict__ outl, int N)
{
    constexpr int VC2 = D / 64;
    constexpr ull ABSM = 0x7FFFFFFF7FFFFFFFULL;
    constexpr float C6 = 0.6f * 1.4426950408889634f;
    constexpr float C4 = 0.4f * 1.4426950408889634f;
    const int w    = (int)((blockIdx.x * (unsigned)blockDim.x + threadIdx.x) >> 5);
    const int lane = threadIdx.x & 31;
    if (w >= N) return;

    ull q2[VC2], a6[VC2], a4[VC2], acc2[VC2];
    if (VC2 == 2) {
        const ulonglong2 t = ((const ulonglong2*)q)[(size_t)w * 32 + lane];
        q2[0] = t.x; q2[1] = t.y;
        const float4 u = ((const float4*)a)[lane];
        a6[0] = pack2(u.x * C6, u.y * C6); a6[1] = pack2(u.z * C6, u.w * C6);
        a4[0] = pack2(u.x * C4, u.y * C4); a4[1] = pack2(u.z * C4, u.w * C4);
    } else {
        q2[0] = ((const ull*)q)[(size_t)w * 32 + lane];
        const float2 u = ((const float2*)a)[lane];
        a6[0] = pack2(u.x * C6, u.y * C6);
        a4[0] = pack2(u.x * C4, u.y * C4);
    }
    #pragma unroll
    for (int i = 0; i < VC2; i++) acc2[i] = 0ULL;

    const int num = min(degp[w], ELLW);
    const int* rowp = ell + (size_t)w * ELLW;
    float den = 0.f;

    for (int base = 0; base < num; base += 32) {
        const int cnt = min(32, num - base);
        const int sl = (base + lane < num) ? rowp[base + lane] : 0;

        ull pv0[VC2], pv1[VC2], pn0[VC2], pn1[VC2];
        {
            const int s0 = __shfl_sync(0xffffffffu, sl, 0);
            const int s1 = __shfl_sync(0xffffffffu, sl, min(1, cnt - 1));
            if (VC2 == 2) {
                ulonglong2 t0 = ((const ulonglong2*)p)[(size_t)s0 * 32 + lane];
                pv0[0] = t0.x; pv0[1] = t0.y;
                ulonglong2 t1 = ((const ulonglong2*)p)[(size_t)s1 * 32 + lane];
                pv1[0] = t1.x; pv1[1] = t1.y;
            } else {
                pv0[0] = ((const ull*)p)[(size_t)s0 * 32 + lane];
                pv1[0] = ((const ull*)p)[(size_t)s1 * 32 + lane];
            }
        }

        for (int j = 0; j < cnt; j += 2) {
            {
                const int sA = __shfl_sync(0xffffffffu, sl, min(j + 2, cnt - 1));
                const int sB = __shfl_sync(0xffffffffu, sl, min(j + 3, cnt - 1));
                if (VC2 == 2) {
                    ulonglong2 tA = ((const ulonglong2*)p)[(size_t)sA * 32 + lane];
                    pn0[0] = tA.x; pn0[1] = tA.y;
                    ulonglong2 tB = ((const ulonglong2*)p)[(size_t)sB * 32 + lane];
                    pn1[0] = tB.x; pn1[1] = tB.y;
                } else {
                    pn0[0] = ((const ull*)p)[(size_t)sA * 32 + lane];
                    pn1[0] = ((const ull*)p)[(size_t)sB * 32 + lane];
                }
            }
            ull part0 = 0ULL, part1 = 0ULL;
            #pragma unroll
            for (int i = 0; i < VC2; i++) {
                const ull v0 = add2(q2[i], pv0[i]);
                part0 = ffma2(v0, a6[i], part0);
                part0 = ffma2(v0 & ABSM, a4[i], part0);
                const ull v1 = add2(q2[i], pv1[i]);
                part1 = ffma2(v1, a6[i], part1);
                part1 = ffma2(v1 & ABSM, a4[i], part1);
            }
            float s0lo, s0hi, s1lo, s1hi;
            unpack2(part0, s0lo, s0hi);
            unpack2(part1, s1lo, s1hi);
            float sc0 = s0lo + s0hi;
            float sc1 = s1lo + s1hi;
            #pragma unroll
            for (int off = 16; off; off >>= 1) {
                sc0 += __shfl_xor_sync(0xffffffffu, sc0, off);
                sc1 += __shfl_xor_sync(0xffffffffu, sc1, off);
            }
            const float ev0 = ex2f(sc0);
            const float ev1 = (j + 1 < cnt) ? ex2f(sc1) : 0.f;
            den += ev0 + ev1;
            const ull e0d = dup2(ev0);
            const ull e1d = dup2(ev1);
            #pragma unroll
            for (int i = 0; i < VC2; i++) {
                acc2[i] = ffma2(e0d, pv0[i], acc2[i]);
                acc2[i] = ffma2(e1d, pv1[i], acc2[i]);
                pv0[i] = pn0[i];
                pv1[i] = pn1[i];
            }
        }
    }

    const float inv = (num > 0) ? (1.f / den) : 0.f;
    if (VC2 == 2) {
        float o0, o1, o2, o3;
        unpack2(acc2[0], o0, o1);
        unpack2(acc2[1], o2, o3);
        o0 *= inv; o1 *= inv; o2 *= inv; o3 *= inv;
        if (M2OUT) {
            const float4 b = ((const float4*)outbias)[lane];   // bg2
            o0 = gelu_erf(o0 + b.x); o1 = gelu_erf(o1 + b.y);
            o2 = gelu_erf(o2 + b.z); o3 = gelu_erf(o3 + b.w);
            __nv_bfloat16 h0, h1, h2, h3, l0, l1, l2, l3;
            split_bf16(o0, h0, l0); split_bf16(o1, h1, l1);
            split_bf16(o2, h2, l2); split_bf16(o3, h3, l3);
            __nv_bfloat162 ph0 = __nv_bfloat162(h0, h1), ph1 = __nv_bfloat162(h2, h3);
            __nv_bfloat162 pl0 = __nv_bfloat162(l0, l1), pl1 = __nv_bfloat162(l2, l3);
            uint2 uh, ul2;
            uh.x = *(u32*)&ph0; uh.y = *(u32*)&ph1;
            ul2.x = *(u32*)&pl0; ul2.y = *(u32*)&pl1;
            ((uint2*)outh)[(size_t)w * 32 + lane] = uh;
            ((uint2*)outl)[(size_t)w * 32 + lane] = ul2;
        } else {
            float4 o = make_float4(o0, o1, o2, o3);
            if (BIAS) {
                const float4 b = ((const float4*)outbias)[lane];
                o.x += b.x; o.y += b.y; o.z += b.z; o.w += b.w;
            }
            ((float4*)out)[(size_t)w * 32 + lane] = o;
        }
    } else {
        float o0, o1;
        unpack2(acc2[0], o0, o1);
        float2 o = make_float2(o0 * inv, o1 * inv);
        if (BIAS) {
            const float2 b = ((const float2*)outbias)[lane];
            o.x += b.x; o.y += b.y;
        }
        ((float2*)out)[(size_t)w * 32 + lane] = o;
    }
}

extern "C" void kernel_launch(void* const* d_in, const int* in_sizes, int n_in,
                              void* d_out, int out_size)
{
    const float* x    = (const float*)d_in[0];
    const float* W0   = (const float*)d_in[1];
    const float* b0   = (const float*)d_in[2];
    const float* Wq1  = (const float*)d_in[3];
    const float* bq1  = (const float*)d_in[4];
    const float* Wp1  = (const float*)d_in[5];
    const float* bp1  = (const float*)d_in[6];
    const float* a1   = (const float*)d_in[7];
    const float* bg2  = (const float*)d_in[8];
    const float* Wq2  = (const float*)d_in[9];
    const float* bq2  = (const float*)d_in[10];
    const float* Wp2  = (const float*)d_in[11];
    const float* bp2  = (const float*)d_in[12];
    const float* a2   = (const float*)d_in[13];
    const float* bout = (const float*)d_in[14];
    const int*   src  = (const int*)d_in[15];
    const int*   dst  = (const int*)d_in[16];
    const int E = in_sizes[15];
    const int N = in_sizes[0] / 128;
    float* out = (float*)d_out;

    u8 *m1h, *m1l, *m2h, *m2l, *wimg;
    float *q1p, *p1p, *q2p, *p2p;
    int *curp, *ellp;
    cudaGetSymbolAddress((void**)&m1h,  g_m1h);
    cudaGetSymbolAddress((void**)&m1l,  g_m1l);
    cudaGetSymbolAddress((void**)&m2h,  g_m2h);
    cudaGetSymbolAddress((void**)&m2l,  g_m2l);
    cudaGetSymbolAddress((void**)&q1p,  g_q1);
    cudaGetSymbolAddress((void**)&p1p,  g_p1);
    cudaGetSymbolAddress((void**)&q2p,  g_q2);
    cudaGetSymbolAddress((void**)&p2p,  g_p2);
    cudaGetSymbolAddress((void**)&curp, g_cur);
    cudaGetSymbolAddress((void**)&ellp, g_ell);
    cudaGetSymbolAddress((void**)&wimg, g_wimg);

    cudaFuncSetAttribute(mma_gemm_k<true, true>,
                         cudaFuncAttributeMaxDynamicSharedMemorySize, GSMEM_SZ);
    cudaFuncSetAttribute(mma_gemm_k<false, false>,
                         cudaFuncAttributeMaxDynamicSharedMemorySize, GSMEM_SZ);

    const int gb = (N + 127) / 128;
    const int pullb = (N * 32 + 255) / 256;

    // 0: weight panels + cur zero
    prep_k<<<256, 256>>>(W0, Wq1, Wp1, Wq2, Wp2, wimg, curp, N);
    // 1: ELL build
    ell_fill_k<<<(E + 255) / 256, 256>>>(src, dst, curp, ellp, E);
    // 2: layer 0 GEMM: m1 = gelu(x @ W0 + b0) -> bf16 hi/lo (reads fp32 x directly)
    mma_gemm_k<true, true><<<dim3(gb, 2), 256, GSMEM_SZ>>>(
        nullptr, nullptr, x, wimg, b0, nullptr, m1h, m1l, 2, 128, N);
    // 3 (profiled): layer 1 GEMM: q1 (y=0,1), p1 (y=2,3)
    mma_gemm_k<false, false><<<dim3(gb, 4), 256, GSMEM_SZ>>>(
        m1h, m1l, nullptr, wimg + 2 * PANEL_SZ, bq1, bp1, q1p, p1p, 2, 128, N);
    // 4: layer 1 pull -> m2 = gelu(agg + bg2) bf16 hi/lo
    gat_pull_k<128, false, true><<<pullb, 256>>>(
        q1p, p1p, a1, curp, ellp, bg2, nullptr, m2h, m2l, N);
    // 5: layer 2 GEMM: q2 (y=0), p2 (y=1)
    mma_gemm_k<false, false><<<dim3(gb, 2), 256, GSMEM_SZ>>>(
        m2h, m2l, nullptr, wimg + 6 * PANEL_SZ, bq2, bp2, q2p, p2p, 1, 64, N);
    // 6: layer 2 pull -> out
    gat_pull_k<64, true, false><<<pullb, 256>>>(
        q2p, p2p, a2, curp, ellp, bout, out, nullptr, nullptr, N);
}